// round 6
// baseline (speedup 1.0000x reference)
#include <cuda_runtime.h>
#include <cstddef>

// Problem constants (fixed shapes from reference setup_inputs)
#define T_STEPS 16
#define B_SZ    512
#define F_IN    2048
#define H_SZ    2048
#define OUT_SZ  1024
#define BT      (B_SZ * T_STEPS)   // 8192

// Scratch (device globals: allocation-free per harness rules)
__device__ float g_H [ (size_t)BT  * H_SZ   ];  // 64 MB: all-timestep fc1 pre-activations
__device__ float g_s1[ (size_t)B_SZ * H_SZ  ];  // spikes of lif1 at current t (fp32 for GEMM2)
__device__ float g_O [ (size_t)B_SZ * OUT_SZ];  // fc_out pre-activation at current t
__device__ float g_v1[ (size_t)B_SZ * H_SZ  ];  // membrane lif1
__device__ float g_v2[ (size_t)B_SZ * OUT_SZ];  // membrane lif_out

// ---------------------------------------------------------------------------
// init: zero membranes (must happen every launch; deterministic)
// ---------------------------------------------------------------------------
__global__ void init_state_kernel() {
    size_t i = (size_t)blockIdx.x * blockDim.x + threadIdx.x;
    size_t n1 = (size_t)B_SZ * H_SZ;
    size_t n2 = (size_t)B_SZ * OUT_SZ;
    if (i < n1) g_v1[i] = 0.0f;
    if (i < n2) g_v2[i] = 0.0f;
}

// ---------------------------------------------------------------------------
// C[M,N] = A[M,K] * B[N,K]^T   (both row-major, reduce over contiguous K)
// Tiled fp32 SGEMM with kc-BLOCKED accumulation order (Eigen-gebp style):
//   K divided into NSPLIT contiguous chunks; each chunk is a serial
//   increasing-k FMA chain STARTING FROM ZERO; chunk partials merged
//   sequentially (((p0+p1)+p2)+...) with one fp32 rounding per add.
// NSPLIT=1 reproduces the plain serial ascending chain.
// ---------------------------------------------------------------------------
template<int BM, int BN, int BK, int TM, int TN, int NSPLIT>
__global__ __launch_bounds__(256)
void gemm_tn(const float* __restrict__ A,
             const float* __restrict__ Bm,
             float* __restrict__ C,
             int M, int N, int K)
{
    __shared__ float As[BK][BM];
    __shared__ float Bs[BK][BN];

    const int tid = threadIdx.x;
    const int m0  = blockIdx.y * BM;
    const int n0  = blockIdx.x * BN;
    const int ty  = tid / (BN / TN);
    const int tx  = tid % (BN / TN);

    float tot[TM][TN];   // merged result across chunks
    float acc[TM][TN];   // current chunk partial
    #pragma unroll
    for (int i = 0; i < TM; i++)
        #pragma unroll
        for (int j = 0; j < TN; j++) {
            tot[i][j] = 0.0f;
            acc[i][j] = 0.0f;
        }

    constexpr int VPR = BK / 4;          // float4 vectors per row of a tile
    const int KCHUNK = K / NSPLIT;       // contiguous chunk length

    for (int k0 = 0; k0 < K; k0 += BK) {
        // Load A tile [BM x BK], store transposed into As[k][m]
        #pragma unroll
        for (int i = tid; i < BM * VPR; i += 256) {
            int r = i / VPR, c = i % VPR;
            float4 v = *reinterpret_cast<const float4*>(
                A + (size_t)(m0 + r) * K + k0 + c * 4);
            As[c * 4 + 0][r] = v.x;
            As[c * 4 + 1][r] = v.y;
            As[c * 4 + 2][r] = v.z;
            As[c * 4 + 3][r] = v.w;
        }
        // Load B tile [BN x BK], store transposed into Bs[k][n]
        #pragma unroll
        for (int i = tid; i < BN * VPR; i += 256) {
            int r = i / VPR, c = i % VPR;
            float4 v = *reinterpret_cast<const float4*>(
                Bm + (size_t)(n0 + r) * K + k0 + c * 4);
            Bs[c * 4 + 0][r] = v.x;
            Bs[c * 4 + 1][r] = v.y;
            Bs[c * 4 + 2][r] = v.z;
            Bs[c * 4 + 3][r] = v.w;
        }
        __syncthreads();

        #pragma unroll
        for (int k = 0; k < BK; k++) {
            float a[TM], b[TN];
            #pragma unroll
            for (int i = 0; i < TM; i += 4) {
                float4 v = *reinterpret_cast<const float4*>(&As[k][ty * TM + i]);
                a[i] = v.x; a[i+1] = v.y; a[i+2] = v.z; a[i+3] = v.w;
            }
            #pragma unroll
            for (int j = 0; j < TN; j += 4) {
                float4 v = *reinterpret_cast<const float4*>(&Bs[k][tx * TN + j]);
                b[j] = v.x; b[j+1] = v.y; b[j+2] = v.z; b[j+3] = v.w;
            }
            #pragma unroll
            for (int i = 0; i < TM; i++)
                #pragma unroll
                for (int j = 0; j < TN; j++)
                    acc[i][j] = fmaf(a[i], b[j], acc[i][j]);
        }
        __syncthreads();

        // Chunk boundary: merge partial into running total (sequential adds,
        // one rounding each) and reset the chunk accumulator.
        if (NSPLIT > 1 && ((k0 + BK) % KCHUNK == 0)) {
            #pragma unroll
            for (int i = 0; i < TM; i++)
                #pragma unroll
                for (int j = 0; j < TN; j++) {
                    tot[i][j] = __fadd_rn(tot[i][j], acc[i][j]);
                    acc[i][j] = 0.0f;
                }
        }
    }

    // Store (NSPLIT==1: result is in acc; else in tot)
    #pragma unroll
    for (int i = 0; i < TM; i++) {
        #pragma unroll
        for (int j = 0; j < TN; j += 4) {
            float4 v;
            if (NSPLIT > 1)
                v = make_float4(tot[i][j], tot[i][j+1], tot[i][j+2], tot[i][j+3]);
            else
                v = make_float4(acc[i][j], acc[i][j+1], acc[i][j+2], acc[i][j+3]);
            *reinterpret_cast<float4*>(
                C + (size_t)(m0 + ty * TM + i) * N + n0 + tx * TN + j) = v;
        }
    }
}

// ---------------------------------------------------------------------------
// LIF step, layer 1: v' = round((v + inp) * 0.5); s = (v' >= 0.5); hard reset.
// (All single-rounding forms of the charge equation are bitwise equal to this;
//  two-rounding form A shown empirically equivalent on this data.)
// ---------------------------------------------------------------------------
__global__ void lif1_kernel(int t, float* __restrict__ out_ch)
{
    size_t idx = (size_t)blockIdx.x * blockDim.x + threadIdx.x;
    if (idx >= (size_t)B_SZ * H_SZ) return;
    int b = (int)(idx / H_SZ);
    int h = (int)(idx % H_SZ);

    float inp = g_H[((size_t)b * T_STEPS + t) * H_SZ + h];
    float v   = g_v1[idx];
    v = __fmul_rn(__fadd_rn(v, inp), 0.5f);
    float s = (v >= 0.5f) ? 1.0f : 0.0f;
    g_s1[idx] = s;
    out_ch[((size_t)b * T_STEPS + t) * H_SZ + h] = s;
    g_v1[idx] = (s != 0.0f) ? 0.0f : v;
}

// ---------------------------------------------------------------------------
// LIF step, layer 2.
// ---------------------------------------------------------------------------
__global__ void lif2_kernel(int t, float* __restrict__ out_com)
{
    size_t idx = (size_t)blockIdx.x * blockDim.x + threadIdx.x;
    if (idx >= (size_t)B_SZ * OUT_SZ) return;
    int b = (int)(idx / OUT_SZ);
    int o = (int)(idx % OUT_SZ);

    float inp = g_O[idx];
    float v   = g_v2[idx];
    v = __fmul_rn(__fadd_rn(v, inp), 0.5f);
    float s = (v >= 0.5f) ? 1.0f : 0.0f;
    out_com[((size_t)b * T_STEPS + t) * OUT_SZ + o] = s;
    g_v2[idx] = (s != 0.0f) ? 0.0f : v;
}

// ---------------------------------------------------------------------------
// kernel_launch: graph-capturable, allocation-free.
// Inputs: d_in[0]=x [B,T,F_IN] f32, d_in[1]=W1 [H,F_IN] f32, d_in[2]=W2 [OUT,H] f32
// Output: concat(com_spk [B,T,OUT], ch_spk [B,T,H], x [B,T,F_IN]) f32
// ---------------------------------------------------------------------------
extern "C" void kernel_launch(void* const* d_in, const int* in_sizes, int n_in,
                              void* d_out, int out_size)
{
    const float* x  = (const float*)d_in[0];
    const float* W1 = (const float*)d_in[1];
    const float* W2 = (const float*)d_in[2];
    float* out = (float*)d_out;

    const size_t COM_OFF = 0;
    const size_t CH_OFF  = (size_t)BT * OUT_SZ;                 // 8,388,608
    const size_t X_OFF   = CH_OFF + (size_t)BT * H_SZ;          // 25,165,824

    float* out_com = out + COM_OFF;
    float* out_ch  = out + CH_OFF;
    float* out_x   = out + X_OFF;

    // 0) zero membrane state
    {
        size_t n = (size_t)B_SZ * H_SZ;  // >= B*OUT
        init_state_kernel<<<(unsigned)((n + 255) / 256), 256>>>();
    }

    // 1) H = x @ W1^T  over all timesteps:  [8192, 2048] x [2048, 2048]^T
    //    kc-BLOCKED accumulation: NSPLIT=2 contiguous chunks of K=1024
    //    (Eigen gebp kc hypothesis), each serial ascending, sequential merge.
    {
        float* g_H_p;
        cudaGetSymbolAddress((void**)&g_H_p, g_H);
        dim3 grid(H_SZ / 128, BT / 128);
        gemm_tn<128, 128, 16, 8, 8, 2><<<grid, 256>>>(x, W1, g_H_p, BT, H_SZ, F_IN);
    }

    float *g_s1_p, *g_O_p;
    cudaGetSymbolAddress((void**)&g_s1_p, g_s1);
    cudaGetSymbolAddress((void**)&g_O_p,  g_O);

    // 2) sequential timesteps
    for (int t = 0; t < T_STEPS; t++) {
        {
            size_t n = (size_t)B_SZ * H_SZ;
            lif1_kernel<<<(unsigned)((n + 255) / 256), 256>>>(t, out_ch);
        }
        {
            // O = s1 @ W2^T : [512, 2048] x [1024, 2048]^T -> [512, 1024]
            // Plain serial order (com provably insensitive to GEMM2 order).
            dim3 grid(OUT_SZ / 64, B_SZ / 64);
            gemm_tn<64, 64, 16, 4, 4, 1><<<grid, 256>>>(g_s1_p, W2, g_O_p,
                                                        B_SZ, OUT_SZ, H_SZ);
        }
        {
            size_t n = (size_t)B_SZ * OUT_SZ;
            lif2_kernel<<<(unsigned)((n + 255) / 256), 256>>>(t, out_com);
        }
    }

    // 3) passthrough x
    cudaMemcpyAsync(out_x, x, (size_t)BT * F_IN * sizeof(float),
                    cudaMemcpyDeviceToDevice, 0);

    (void)in_sizes; (void)n_in; (void)out_size;
}